// round 1
// baseline (speedup 1.0000x reference)
#include <cuda_runtime.h>
#include <cstdint>

#define B_   256
#define N_   144
#define D_   512
#define H_   8
#define HD_  64
#define M_   (B_ * N_)            // 36864 rows
#define SCALE_ 0.125f             // 64^-0.5

// ---------------- scratch (device globals: allocation-free rule) -------------
__device__ float g_kv [(size_t)M_ * 1024];   // [m, {k:0..511 | v:512..1023}], col = h*64+e
__device__ float g_q  [(size_t)M_ * 512];    // [m, h*64+e]
__device__ float g_att[(size_t)M_ * 512];    // [m, h*64+e]  (== [b,n,h,e] -> matches final reshape)

// ---------------- packed f32x2 helpers (Blackwell FFMA2 path) ----------------
__device__ __forceinline__ unsigned long long pack2(float lo, float hi) {
    unsigned long long r;
    asm("mov.b64 %0, {%1, %2};" : "=l"(r) : "f"(lo), "f"(hi));
    return r;
}
__device__ __forceinline__ void fma2(unsigned long long& d, unsigned long long a, unsigned long long b) {
    asm("fma.rn.f32x2 %0, %1, %2, %0;" : "+l"(d) : "l"(a), "l"(b));
}
__device__ __forceinline__ float2 unpack2(unsigned long long v) {
    float2 r;
    asm("mov.b64 {%0, %1}, %2;" : "=f"(r.x), "=f"(r.y) : "l"(v));
    return r;
}

// ---------------- SGEMM:  C[M x Nc] = (A (+ f*A2)) @ W^T (+ bias) -------------
// A: [M,512] row-major, W: [Nc,512] row-major (both K-contiguous -> NT dot products)
// 128x128x16 tile, 256 threads, 8x8 micro-tile per thread, f32x2 accumulate.
__global__ __launch_bounds__(256)
void gemm_nt_kernel(const float* __restrict__ A, const float* __restrict__ A2,
                    const int* __restrict__ flag,
                    const float* __restrict__ W, const float* __restrict__ bias,
                    float* __restrict__ C, int Nc)
{
    __shared__ float As[16][132];
    __shared__ float Ws[16][132];

    const int t    = threadIdx.x;
    const int row0 = blockIdx.y * 128;
    const int col0 = blockIdx.x * 128;
    const int lr   = t >> 2;          // 0..63
    const int lc   = (t & 3) << 2;    // 0,4,8,12
    const int tx   = t & 15;
    const int ty   = t >> 4;

    float addf = 0.f;
    if (A2) addf = (*flag != 0) ? 1.f : 0.f;

    unsigned long long acc[8][4];
#pragma unroll
    for (int i = 0; i < 8; i++)
#pragma unroll
        for (int j = 0; j < 4; j++) acc[i][j] = 0ull;

    const float* Abase  = A + (size_t)(row0 + lr) * 512 + lc;
    const float* A2base = A2 ? (A2 + (size_t)(row0 + lr) * 512 + lc) : nullptr;
    const float* Wbase  = W + (size_t)(col0 + lr) * 512 + lc;

    for (int k0 = 0; k0 < 512; k0 += 16) {
        float4 a0 = *(const float4*)(Abase + k0);
        float4 a1 = *(const float4*)(Abase + (size_t)64 * 512 + k0);
        if (A2) {
            float4 t0 = *(const float4*)(A2base + k0);
            float4 t1 = *(const float4*)(A2base + (size_t)64 * 512 + k0);
            a0.x += addf * t0.x; a0.y += addf * t0.y; a0.z += addf * t0.z; a0.w += addf * t0.w;
            a1.x += addf * t1.x; a1.y += addf * t1.y; a1.z += addf * t1.z; a1.w += addf * t1.w;
        }
        float4 w0 = *(const float4*)(Wbase + k0);
        float4 w1 = *(const float4*)(Wbase + (size_t)64 * 512 + k0);

        __syncthreads();   // previous tile's compute done before overwrite
        As[lc + 0][lr]      = a0.x; As[lc + 1][lr]      = a0.y;
        As[lc + 2][lr]      = a0.z; As[lc + 3][lr]      = a0.w;
        As[lc + 0][lr + 64] = a1.x; As[lc + 1][lr + 64] = a1.y;
        As[lc + 2][lr + 64] = a1.z; As[lc + 3][lr + 64] = a1.w;
        Ws[lc + 0][lr]      = w0.x; Ws[lc + 1][lr]      = w0.y;
        Ws[lc + 2][lr]      = w0.z; Ws[lc + 3][lr]      = w0.w;
        Ws[lc + 0][lr + 64] = w1.x; Ws[lc + 1][lr + 64] = w1.y;
        Ws[lc + 2][lr + 64] = w1.z; Ws[lc + 3][lr + 64] = w1.w;
        __syncthreads();

#pragma unroll
        for (int kk = 0; kk < 16; kk++) {
            float4 av0 = *(const float4*)&As[kk][ty * 8];
            float4 av1 = *(const float4*)&As[kk][ty * 8 + 4];
            float4 bv0 = *(const float4*)&Ws[kk][tx * 8];
            float4 bv1 = *(const float4*)&Ws[kk][tx * 8 + 4];
            unsigned long long bp[4] = { pack2(bv0.x, bv0.y), pack2(bv0.z, bv0.w),
                                         pack2(bv1.x, bv1.y), pack2(bv1.z, bv1.w) };
            float ar[8] = { av0.x, av0.y, av0.z, av0.w, av1.x, av1.y, av1.z, av1.w };
#pragma unroll
            for (int i = 0; i < 8; i++) {
                unsigned long long ad = pack2(ar[i], ar[i]);
#pragma unroll
                for (int j = 0; j < 4; j++) fma2(acc[i][j], ad, bp[j]);
            }
        }
    }

#pragma unroll
    for (int i = 0; i < 8; i++) {
        size_t row = (size_t)(row0 + ty * 8 + i);
        float* Cp = C + row * (size_t)Nc + col0 + tx * 8;
        float2 r0 = unpack2(acc[i][0]);
        float2 r1 = unpack2(acc[i][1]);
        float2 r2 = unpack2(acc[i][2]);
        float2 r3 = unpack2(acc[i][3]);
        if (bias) {
            const float* bp = bias + col0 + tx * 8;
            r0.x += bp[0]; r0.y += bp[1]; r1.x += bp[2]; r1.y += bp[3];
            r2.x += bp[4]; r2.y += bp[5]; r3.x += bp[6]; r3.y += bp[7];
        }
        *(float4*)(Cp)     = make_float4(r0.x, r0.y, r1.x, r1.y);
        *(float4*)(Cp + 4) = make_float4(r2.x, r2.y, r3.x, r3.y);
    }
}

// ---------------- attention: one block per (b, h) -----------------------------
// smem: K [144][68], V [144][68], qrow [8 warps][4 rows][64], prow [8][4][144]
#define KV_PITCH 68
#define ATTN_SMEM_FLOATS (2 * 144 * KV_PITCH + 8 * 4 * 64 + 8 * 4 * 144)
#define ATTN_SMEM_BYTES  (ATTN_SMEM_FLOATS * 4)

__global__ __launch_bounds__(256)
void attn_kernel(const float* __restrict__ q, const float* __restrict__ kv,
                 float* __restrict__ o)
{
    extern __shared__ float sm[];
    float* ks = sm;                          // 144*68
    float* vs = ks + 144 * KV_PITCH;         // 144*68
    float* qs = vs + 144 * KV_PITCH;         // 8*4*64
    float* ps = qs + 8 * 4 * 64;             // 8*4*144

    const int b = blockIdx.x >> 3;
    const int h = blockIdx.x & 7;
    const int t = threadIdx.x;

    const float* kb = kv + (size_t)b * 144 * 1024 + h * 64;
    const float* vb = kb + 512;

    // stage K and V (coalesced float4)
    for (int i = t; i < 144 * 16; i += 256) {
        int n = i >> 4, c = (i & 15) << 2;
        float4 kx = *(const float4*)(kb + (size_t)n * 1024 + c);
        float4 vx = *(const float4*)(vb + (size_t)n * 1024 + c);
        *(float4*)(ks + n * KV_PITCH + c) = kx;
        *(float4*)(vs + n * KV_PITCH + c) = vx;
    }
    __syncthreads();

    const int w    = t >> 5;
    const int lane = t & 31;
    const float* qb = q + (size_t)b * 144 * 512 + h * 64;
    float*       ob = o + (size_t)b * 144 * 512 + h * 64;
    float* qr = qs + w * 256;      // 4 rows x 64
    float* pr = ps + w * 576;      // 4 rows x 144

    for (int r0 = w * 4; r0 < 144; r0 += 32) {
        // load 4 query rows into this warp's smem slab
#pragma unroll
        for (int rr = 0; rr < 4; rr++) {
            qr[rr * 64 + lane]      = qb[(size_t)(r0 + rr) * 512 + lane];
            qr[rr * 64 + lane + 32] = qb[(size_t)(r0 + rr) * 512 + lane + 32];
        }
        __syncwarp();

        // S = q @ k^T : each lane owns keys {lane, lane+32, ...}
        float s[4][5];
#pragma unroll
        for (int jt = 0; jt < 5; jt++) {
            int j = lane + (jt << 5);
            float a0 = 0.f, a1 = 0.f, a2 = 0.f, a3 = 0.f;
            if (j < 144) {
                const float* kr = ks + j * KV_PITCH;
#pragma unroll 4
                for (int d = 0; d < 64; d += 4) {
                    float4 kx = *(const float4*)(kr + d);
                    float4 q0 = *(const float4*)(qr + d);
                    float4 q1 = *(const float4*)(qr + 64 + d);
                    float4 q2 = *(const float4*)(qr + 128 + d);
                    float4 q3 = *(const float4*)(qr + 192 + d);
                    a0 += q0.x * kx.x + q0.y * kx.y + q0.z * kx.z + q0.w * kx.w;
                    a1 += q1.x * kx.x + q1.y * kx.y + q1.z * kx.z + q1.w * kx.w;
                    a2 += q2.x * kx.x + q2.y * kx.y + q2.z * kx.z + q2.w * kx.w;
                    a3 += q3.x * kx.x + q3.y * kx.y + q3.z * kx.z + q3.w * kx.w;
                }
            }
            s[0][jt] = a0 * SCALE_; s[1][jt] = a1 * SCALE_;
            s[2][jt] = a2 * SCALE_; s[3][jt] = a3 * SCALE_;
        }

        // softmax per row (warp-wide)
        float inv[4];
#pragma unroll
        for (int rr = 0; rr < 4; rr++) {
            float m = -1e30f;
#pragma unroll
            for (int jt = 0; jt < 5; jt++) {
                int j = lane + (jt << 5);
                if (j < 144) m = fmaxf(m, s[rr][jt]);
            }
#pragma unroll
            for (int off = 16; off; off >>= 1)
                m = fmaxf(m, __shfl_xor_sync(0xffffffffu, m, off));
            float sum = 0.f;
#pragma unroll
            for (int jt = 0; jt < 5; jt++) {
                int j = lane + (jt << 5);
                float e = 0.f;
                if (j < 144) {
                    e = __expf(s[rr][jt] - m);
                    pr[rr * 144 + j] = e;
                }
                sum += e;
            }
#pragma unroll
            for (int off = 16; off; off >>= 1)
                sum += __shfl_xor_sync(0xffffffffu, sum, off);
            inv[rr] = 1.f / sum;
        }
        __syncwarp();

        // O = P @ V : lane owns output dims {2*lane, 2*lane+1}
        float acc[4][2] = {};
#pragma unroll 2
        for (int j0 = 0; j0 < 144; j0 += 4) {
            float4 p0 = *(const float4*)(pr + 0   + j0);
            float4 p1 = *(const float4*)(pr + 144 + j0);
            float4 p2 = *(const float4*)(pr + 288 + j0);
            float4 p3 = *(const float4*)(pr + 432 + j0);
            const float pa[4][4] = {
                { p0.x, p0.y, p0.z, p0.w }, { p1.x, p1.y, p1.z, p1.w },
                { p2.x, p2.y, p2.z, p2.w }, { p3.x, p3.y, p3.z, p3.w } };
#pragma unroll
            for (int u = 0; u < 4; u++) {
                float2 v2 = *(const float2*)(vs + (j0 + u) * KV_PITCH + 2 * lane);
                acc[0][0] += pa[0][u] * v2.x; acc[0][1] += pa[0][u] * v2.y;
                acc[1][0] += pa[1][u] * v2.x; acc[1][1] += pa[1][u] * v2.y;
                acc[2][0] += pa[2][u] * v2.x; acc[2][1] += pa[2][u] * v2.y;
                acc[3][0] += pa[3][u] * v2.x; acc[3][1] += pa[3][u] * v2.y;
            }
        }
#pragma unroll
        for (int rr = 0; rr < 4; rr++) {
            *(float2*)(ob + (size_t)(r0 + rr) * 512 + 2 * lane) =
                make_float2(acc[rr][0] * inv[rr], acc[rr][1] * inv[rr]);
        }
        __syncwarp();
    }
}

// ---------------- launch -------------------------------------------------------
extern "C" void kernel_launch(void* const* d_in, const int* in_sizes, int n_in,
                              void* d_out, int out_size)
{
    const float* x      = (const float*)d_in[0];
    const float* topo   = (const float*)d_in[1];
    const float* kv_w   = (const float*)d_in[2];
    const float* q_w    = (const float*)d_in[3];
    const float* proj_w = (const float*)d_in[4];
    const float* proj_b = (const float*)d_in[5];
    const int*   is_end = (const int*)d_in[6];

    void *pkv = nullptr, *pq = nullptr, *patt = nullptr;
    cudaGetSymbolAddress(&pkv, g_kv);
    cudaGetSymbolAddress(&pq,  g_q);
    cudaGetSymbolAddress(&patt, g_att);
    float* fkv  = (float*)pkv;
    float* fq   = (float*)pq;
    float* fatt = (float*)patt;

    cudaFuncSetAttribute(attn_kernel, cudaFuncAttributeMaxDynamicSharedMemorySize,
                         ATTN_SMEM_BYTES);

    // KV = (x + is_end*topo) @ kv_w^T   [36864 x 1024]
    gemm_nt_kernel<<<dim3(8, 288), 256>>>(x, topo, is_end, kv_w, nullptr, fkv, 1024);
    // Q  = x @ q_w^T                    [36864 x 512]
    gemm_nt_kernel<<<dim3(4, 288), 256>>>(x, nullptr, nullptr, q_w, nullptr, fq, 512);
    // per-(b,h) softmax attention       -> g_att [36864 x 512] in [b,n,h,e] order
    attn_kernel<<<B_ * H_, 256, ATTN_SMEM_BYTES>>>(fq, fkv, fatt);
    // out = g_att @ proj_w^T + proj_b   -> d_out
    gemm_nt_kernel<<<dim3(4, 288), 256>>>(fatt, nullptr, nullptr, proj_w, proj_b,
                                          (float*)d_out, 512);
}